// round 5
// baseline (speedup 1.0000x reference)
#include <cuda_runtime.h>
#include <math.h>
#include <stdint.h>

#define HIDDEN 768
#define KEY    128
#define INTER  1536
#define BDIM   4
#define SEQ    2048
#define M_TOT  (BDIM*SEQ)        // 8192
#define N1     (2*INTER+KEY)     // 3200

#define BM 128
#define BN 128
#define BK 16
#define STAGES 4
#define A_LD 20      // frag LDS banks (20*row+tg) all distinct mod 32
#define B_LD 136     // frag LDS banks (8*tg+gp) all distinct mod 32
#define A_STAGE (BM * A_LD)
#define B_STAGE (BK * B_LD)
#define SMEM_BYTES ((STAGES * (A_STAGE + B_STAGE)) * 4)   // 75,776 B -> 2 CTAs/SM

// ---------------- scratch (device globals; no allocation allowed) ----------
__device__ float g_u[(size_t)M_TOT * INTER];           // u (raw), then tf32(u*ctx)
__device__ float g_v[(size_t)M_TOT * INTER];           // tf32-rounded v
__device__ float g_q[(size_t)M_TOT * KEY];             // tf32-rounded q
__device__ float g_kT[(size_t)BDIM * KEY * SEQ];       // tf32-rounded k, transposed
__device__ float g_scores[(size_t)BDIM * SEQ * SEQ];   // scores -> tf32 attn in place
__device__ float g_hs[(size_t)M_TOT * HIDDEN];         // tf32-rounded hidden_states
__device__ float g_wi[(size_t)HIDDEN * N1];            // tf32-rounded Wi
__device__ float g_wo[(size_t)INTER * HIDDEN];         // tf32-rounded Wo

// ---------------- helpers ---------------------------------------------------
__device__ __forceinline__ float to_tf32(float x) {
    float r;
    asm("cvt.rna.tf32.f32 %0, %1;" : "=f"(r) : "f"(x));
    return r;
}

__device__ __forceinline__ void mma_tf32(float (&c)[4], const uint32_t (&a)[4],
                                         const uint32_t (&b)[2]) {
    asm volatile(
        "mma.sync.aligned.m16n8k8.row.col.f32.tf32.tf32.f32 "
        "{%0,%1,%2,%3}, {%4,%5,%6,%7}, {%8,%9}, {%0,%1,%2,%3};"
        : "+f"(c[0]), "+f"(c[1]), "+f"(c[2]), "+f"(c[3])
        : "r"(a[0]), "r"(a[1]), "r"(a[2]), "r"(a[3]), "r"(b[0]), "r"(b[1]));
}

__device__ __forceinline__ void cp_async16(float* smem, const float* gmem) {
    uint32_t s = (uint32_t)__cvta_generic_to_shared(smem);
    asm volatile("cp.async.cg.shared.global [%0], [%1], 16;" :: "r"(s), "l"(gmem));
}
#define CP_COMMIT() asm volatile("cp.async.commit_group;")
#define CP_WAIT2()  asm volatile("cp.async.wait_group 2;")

// ---------------- 4-stage pipelined tf32 GEMM core ---------------------------
// 256 threads = 8 warps (2x4); warp tile 64x32; block tile 128x128; BK=16.
// A: [M][K] row-major (tf32-rounded). B: [K][N] row-major (tf32-rounded).
// Dynamic smem: STAGES x (A tile + B tile). One __syncthreads per k-iter.
// wait_group 2 keeps 2 newer stages in flight while computing stage `it`.
template <int KDIM>
__device__ __forceinline__ void gemm_tf32(const float* __restrict__ A,
                                          const float* __restrict__ B,
                                          int lda, int ldb,
                                          int m0, int n0,
                                          float (&acc)[4][4][4]) {
    extern __shared__ float sm[];
    float* Abuf = sm;                        // STAGES * A_STAGE
    float* Bbuf = sm + STAGES * A_STAGE;     // STAGES * B_STAGE

    const int tid  = threadIdx.x;
    const int lane = tid & 31;
    const int warp = tid >> 5;
    const int wr   = warp >> 2;   // 0..1 -> m offset 64
    const int wc   = warp & 3;    // 0..3 -> n offset 32
    const int gp   = lane >> 2;   // 0..7
    const int tg   = lane & 3;    // 0..3

    constexpr int NIT = KDIM / BK;

    // issue stage for iteration `it` into buffer it%STAGES; ALWAYS commits.
    auto issue = [&](int it) {
        if (it < NIT) {
            const int k0 = it * BK;
            float* As = Abuf + (it % STAGES) * A_STAGE;
            float* Bs = Bbuf + (it % STAGES) * B_STAGE;
            #pragma unroll
            for (int t = 0; t < 2; t++) {
                const int id = tid + t * 256;       // 0..511
                const int ar = id >> 2;             // 0..127
                const int ac = (id & 3) * 4;        // 0..12
                cp_async16(As + ar * A_LD + ac,
                           A + (size_t)(m0 + ar) * lda + k0 + ac);
            }
            #pragma unroll
            for (int t = 0; t < 2; t++) {
                const int id = tid + t * 256;
                const int br = id >> 5;             // 0..15
                const int bc = (id & 31) * 4;       // 0..124
                cp_async16(Bs + br * B_LD + bc,
                           B + (size_t)(k0 + br) * ldb + n0 + bc);
            }
        }
        CP_COMMIT();
    };

    issue(0);
    issue(1);
    issue(2);

    for (int it = 0; it < NIT; ++it) {
        CP_WAIT2();          // stage `it` done; 2 newer stages may be in flight
        __syncthreads();     // also guards reuse of buffer (it+3)%4 below
        issue(it + 3);

        const float* As = Abuf + (it % STAGES) * A_STAGE;
        const float* Bs = Bbuf + (it % STAGES) * B_STAGE;

        #pragma unroll
        for (int kk = 0; kk < BK; kk += 8) {
            uint32_t a[4][4], b[4][2];
            #pragma unroll
            for (int mi = 0; mi < 4; mi++) {
                const int row = wr * 64 + mi * 16 + gp;
                a[mi][0] = __float_as_uint(As[(row    ) * A_LD + kk + tg    ]);
                a[mi][1] = __float_as_uint(As[(row + 8) * A_LD + kk + tg    ]);
                a[mi][2] = __float_as_uint(As[(row    ) * A_LD + kk + tg + 4]);
                a[mi][3] = __float_as_uint(As[(row + 8) * A_LD + kk + tg + 4]);
            }
            #pragma unroll
            for (int nj = 0; nj < 4; nj++) {
                const int col = wc * 32 + nj * 8 + gp;
                b[nj][0] = __float_as_uint(Bs[(kk + tg    ) * B_LD + col]);
                b[nj][1] = __float_as_uint(Bs[(kk + tg + 4) * B_LD + col]);
            }
            #pragma unroll
            for (int mi = 0; mi < 4; mi++)
                #pragma unroll
                for (int nj = 0; nj < 4; nj++)
                    mma_tf32(acc[mi][nj], a[mi], b[nj]);
        }
    }
}

// Epilogue indices: m = m0 + wr*64 + mi*16 + gp + (e>=2 ? 8 : 0)
//                   n = n0 + wc*32 + nj*8 + 2*tg + (e&1)

// ---------------- prepass: tf32-round an array -------------------------------
__global__ __launch_bounds__(256) void k_round(const float4* __restrict__ src,
                                               float4* __restrict__ dst, int n4) {
    const int i = blockIdx.x * 256 + threadIdx.x;
    if (i < n4) {
        const float4 v = src[i];
        dst[i] = make_float4(to_tf32(v.x), to_tf32(v.y), to_tf32(v.z), to_tf32(v.w));
    }
}

// ---------------- kernel 1: h = silu(X @ Wi + bi), split u/v/q/kT ------------
__global__ __launch_bounds__(256, 2) void k_gemm1(const float* __restrict__ bi,
                                                  const float* __restrict__ gamma,
                                                  const float* __restrict__ beta) {
    float acc[4][4][4] = {};
    const int m0 = blockIdx.y * BM;
    const int n0 = blockIdx.x * BN;
    gemm_tf32<HIDDEN>(g_hs, g_wi, HIDDEN, N1, m0, n0, acc);

    const int lane = threadIdx.x & 31, warp = threadIdx.x >> 5;
    const int wr = warp >> 2, wc = warp & 3, gp = lane >> 2, tg = lane & 3;

    #pragma unroll
    for (int mi = 0; mi < 4; mi++)
        #pragma unroll
        for (int nj = 0; nj < 4; nj++)
            #pragma unroll
            for (int e = 0; e < 4; e++) {
                const int m = m0 + wr * 64 + mi * 16 + gp + ((e >> 1) << 3);
                const int n = n0 + wc * 32 + nj * 8 + 2 * tg + (e & 1);
                const float x = acc[mi][nj][e] + bi[n];
                const float sv = x / (1.0f + expf(-x));   // silu
                if (n0 < INTER) {
                    g_u[(size_t)m * INTER + n] = sv;                       // raw
                } else if (n0 < 2 * INTER) {
                    g_v[(size_t)m * INTER + (n - INTER)] = to_tf32(sv);
                } else {
                    const int c = n - 2 * INTER;
                    const int b = m >> 11;         // m / SEQ
                    const int s = m & (SEQ - 1);   // m % SEQ
                    g_q[(size_t)m * KEY + c] = to_tf32(sv * gamma[c] + beta[c]);
                    g_kT[((size_t)b * KEY + c) * SEQ + s] =
                        to_tf32(sv * gamma[KEY + c] + beta[KEY + c]);
                }
            }
}

// ---------------- kernel 2: scores = q @ k^T / sqrt(KEY) + mask --------------
__global__ __launch_bounds__(256, 2) void k_scores(const int* __restrict__ mask) {
    const int b = blockIdx.z;
    float acc[4][4][4] = {};
    const int m0 = blockIdx.y * BM;
    const int n0 = blockIdx.x * BN;
    gemm_tf32<KEY>(g_q + (size_t)b * SEQ * KEY,
                   g_kT + (size_t)b * KEY * SEQ,
                   KEY, SEQ, m0, n0, acc);

    float* sc = g_scores + (size_t)b * SEQ * SEQ;
    const float inv = 0.08838834764831845f;  // 1/sqrt(128)
    const int lane = threadIdx.x & 31, warp = threadIdx.x >> 5;
    const int wr = warp >> 2, wc = warp & 3, gp = lane >> 2, tg = lane & 3;

    #pragma unroll
    for (int nj = 0; nj < 4; nj++) {
        const int n = n0 + wc * 32 + nj * 8 + 2 * tg;
        const float am0 = (1.0f - (float)mask[b * SEQ + n    ]) * -1.0e12f;
        const float am1 = (1.0f - (float)mask[b * SEQ + n + 1]) * -1.0e12f;
        #pragma unroll
        for (int mi = 0; mi < 4; mi++) {
            const int m = m0 + wr * 64 + mi * 16 + gp;
            sc[(size_t)m * SEQ + n    ]       = acc[mi][nj][0] * inv + am0;
            sc[(size_t)m * SEQ + n + 1]       = acc[mi][nj][1] * inv + am1;
            sc[(size_t)(m + 8) * SEQ + n    ] = acc[mi][nj][2] * inv + am0;
            sc[(size_t)(m + 8) * SEQ + n + 1] = acc[mi][nj][3] * inv + am1;
        }
    }
}

// ---------------- kernel 3: length-scaled softmax (writes tf32 attn) ---------
__global__ __launch_bounds__(256) void k_softmax() {
    float* sc = g_scores + (size_t)blockIdx.x * SEQ;
    const int tid = threadIdx.x;
    __shared__ float red[256];

    float vals[8];
    int cnt = 0;
    #pragma unroll
    for (int t = 0; t < 8; t++) {
        vals[t] = sc[tid + t * 256];
        cnt += (vals[t] > -1.0e11f) ? 1 : 0;
    }
    red[tid] = (float)cnt;
    __syncthreads();
    for (int s = 128; s > 0; s >>= 1) {
        if (tid < s) red[tid] += red[tid + s];
        __syncthreads();
    }
    const float l = fmaxf(red[0], 1.0f);
    const float scale = logf(l) * (1.0f / logf(512.0f));
    __syncthreads();

    float mx = -INFINITY;
    #pragma unroll
    for (int t = 0; t < 8; t++) {
        vals[t] *= scale;
        mx = fmaxf(mx, vals[t]);
    }
    red[tid] = mx;
    __syncthreads();
    for (int s = 128; s > 0; s >>= 1) {
        if (tid < s) red[tid] = fmaxf(red[tid], red[tid + s]);
        __syncthreads();
    }
    mx = red[0];
    __syncthreads();

    float sum = 0.0f;
    #pragma unroll
    for (int t = 0; t < 8; t++) {
        vals[t] = expf(vals[t] - mx);
        sum += vals[t];
    }
    red[tid] = sum;
    __syncthreads();
    for (int s = 128; s > 0; s >>= 1) {
        if (tid < s) red[tid] += red[tid + s];
        __syncthreads();
    }
    const float invsum = 1.0f / red[0];
    #pragma unroll
    for (int t = 0; t < 8; t++)
        sc[tid + t * 256] = to_tf32(vals[t] * invsum);
}

// ---------------- kernel 4: g = tf32(u * (attn @ v)), in place into g_u ------
__global__ __launch_bounds__(256, 2) void k_ctx() {
    const int b = blockIdx.z;
    float acc[4][4][4] = {};
    const int m0 = blockIdx.y * BM;
    const int n0 = blockIdx.x * BN;
    gemm_tf32<SEQ>(g_scores + (size_t)b * SEQ * SEQ,
                   g_v + (size_t)b * SEQ * INTER,
                   SEQ, INTER, m0, n0, acc);

    const int lane = threadIdx.x & 31, warp = threadIdx.x >> 5;
    const int wr = warp >> 2, wc = warp & 3, gp = lane >> 2, tg = lane & 3;

    #pragma unroll
    for (int mi = 0; mi < 4; mi++)
        #pragma unroll
        for (int nj = 0; nj < 4; nj++)
            #pragma unroll
            for (int e = 0; e < 4; e++) {
                const int m = m0 + wr * 64 + mi * 16 + gp + ((e >> 1) << 3);
                const int n = n0 + wc * 32 + nj * 8 + 2 * tg + (e & 1);
                const size_t idx = ((size_t)b * SEQ + m) * INTER + n;
                g_u[idx] = to_tf32(g_u[idx] * acc[mi][nj][e]);
            }
}

// ---------------- kernel 5: out = g @ Wo + bo --------------------------------
__global__ __launch_bounds__(256, 2) void k_out(const float* __restrict__ bo,
                                                float* __restrict__ out) {
    float acc[4][4][4] = {};
    const int m0 = blockIdx.y * BM;
    const int n0 = blockIdx.x * BN;
    gemm_tf32<INTER>(g_u, g_wo, INTER, HIDDEN, m0, n0, acc);

    const int lane = threadIdx.x & 31, warp = threadIdx.x >> 5;
    const int wr = warp >> 2, wc = warp & 3, gp = lane >> 2, tg = lane & 3;

    #pragma unroll
    for (int mi = 0; mi < 4; mi++)
        #pragma unroll
        for (int nj = 0; nj < 4; nj++)
            #pragma unroll
            for (int e = 0; e < 4; e++) {
                const int m = m0 + wr * 64 + mi * 16 + gp + ((e >> 1) << 3);
                const int n = n0 + wc * 32 + nj * 8 + 2 * tg + (e & 1);
                out[(size_t)m * HIDDEN + n] = acc[mi][nj][e] + bo[n];
            }
}

// ---------------- launch ------------------------------------------------------
extern "C" void kernel_launch(void* const* d_in, const int* in_sizes, int n_in,
                              void* d_out, int out_size) {
    const float* hs    = (const float*)d_in[0];
    const int*   mask  = (const int*)  d_in[1];
    // d_in[2] = position_ids (unused)
    const float* Wi    = (const float*)d_in[3];
    const float* bi    = (const float*)d_in[4];
    const float* gamma = (const float*)d_in[5];
    const float* beta  = (const float*)d_in[6];
    const float* Wo    = (const float*)d_in[7];
    const float* bo    = (const float*)d_in[8];
    float* out = (float*)d_out;

    float *p_hs, *p_wi, *p_wo;
    cudaGetSymbolAddress((void**)&p_hs, g_hs);
    cudaGetSymbolAddress((void**)&p_wi, g_wi);
    cudaGetSymbolAddress((void**)&p_wo, g_wo);

    cudaFuncSetAttribute(k_gemm1,  cudaFuncAttributeMaxDynamicSharedMemorySize, SMEM_BYTES);
    cudaFuncSetAttribute(k_scores, cudaFuncAttributeMaxDynamicSharedMemorySize, SMEM_BYTES);
    cudaFuncSetAttribute(k_ctx,    cudaFuncAttributeMaxDynamicSharedMemorySize, SMEM_BYTES);
    cudaFuncSetAttribute(k_out,    cudaFuncAttributeMaxDynamicSharedMemorySize, SMEM_BYTES);

    dim3 blk(256);
    {
        const int n4 = M_TOT * HIDDEN / 4;
        k_round<<<(n4 + 255) / 256, blk>>>((const float4*)hs, (float4*)p_hs, n4);
    }
    {
        const int n4 = HIDDEN * N1 / 4;
        k_round<<<(n4 + 255) / 256, blk>>>((const float4*)Wi, (float4*)p_wi, n4);
    }
    {
        const int n4 = INTER * HIDDEN / 4;
        k_round<<<(n4 + 255) / 256, blk>>>((const float4*)Wo, (float4*)p_wo, n4);
    }

    k_gemm1  <<<dim3(N1 / BN, M_TOT / BM), blk, SMEM_BYTES>>>(bi, gamma, beta);
    k_scores <<<dim3(SEQ / BN, SEQ / BM, BDIM), blk, SMEM_BYTES>>>(mask);
    k_softmax<<<dim3(M_TOT), blk>>>();
    k_ctx    <<<dim3(INTER / BN, SEQ / BM, BDIM), blk, SMEM_BYTES>>>();
    k_out    <<<dim3(HIDDEN / BN, M_TOT / BM), blk, SMEM_BYTES>>>(bo, out);
}

// round 7
// speedup vs baseline: 1.5406x; 1.5406x over previous
#include <cuda_runtime.h>
#include <cuda_fp16.h>
#include <math.h>
#include <stdint.h>

#define HIDDEN 768
#define KEY    128
#define INTER  1536
#define BDIM   4
#define SEQ    2048
#define M_TOT  (BDIM*SEQ)        // 8192
#define N1     (2*INTER+KEY)     // 3200

#define BM 128
#define BN 128
#define BK 32                    // 32 halves = 64 B per row
#define STAGES 4
#define T_LD 40                  // halves per row (20 words): banks 20r+tg distinct mod 32
#define T_STAGE (128 * T_LD)     // halves per tile per stage
#define SMEM_BYTES (STAGES * 2 * T_STAGE * 2)   // 81,920 B -> 2 CTAs/SM

// ---------------- scratch (device globals; no allocation allowed) ----------
__device__ float  g_u[(size_t)M_TOT * INTER];          // u raw fp32
__device__ float  g_v[(size_t)M_TOT * INTER];          // v raw fp32 (transpose source)
__device__ __half g_vT[(size_t)M_TOT * INTER];         // v^T per batch [INTER][SEQ]
__device__ __half g_q[(size_t)M_TOT * KEY];            // q half [m][KEY]
__device__ __half g_k[(size_t)M_TOT * KEY];            // k half [m][KEY]
__device__ float  g_scores[(size_t)BDIM * SEQ * SEQ];  // scores fp32
__device__ __half g_attn[(size_t)BDIM * SEQ * SEQ];    // softmax(attn) half
__device__ __half g_g[(size_t)M_TOT * INTER];          // half(u*ctx)
__device__ __half g_hs[(size_t)M_TOT * HIDDEN];        // half hidden_states
__device__ __half g_wiT[(size_t)N1 * HIDDEN];          // Wi^T [N1][HIDDEN]
__device__ __half g_woT[(size_t)HIDDEN * INTER];       // Wo^T [HIDDEN][INTER]

// ---------------- helpers ---------------------------------------------------
__device__ __forceinline__ float silu(float x) { return x / (1.0f + expf(-x)); }

__device__ __forceinline__ void mma_f16(float (&c)[4], const uint32_t (&a)[4],
                                        const uint32_t (&b)[2]) {
    asm volatile(
        "mma.sync.aligned.m16n8k16.row.col.f32.f16.f16.f32 "
        "{%0,%1,%2,%3}, {%4,%5,%6,%7}, {%8,%9}, {%0,%1,%2,%3};"
        : "+f"(c[0]), "+f"(c[1]), "+f"(c[2]), "+f"(c[3])
        : "r"(a[0]), "r"(a[1]), "r"(a[2]), "r"(a[3]), "r"(b[0]), "r"(b[1]));
}

__device__ __forceinline__ void cp_async16(const __half* smem, const __half* gmem) {
    uint32_t s = (uint32_t)__cvta_generic_to_shared(smem);
    asm volatile("cp.async.cg.shared.global [%0], [%1], 16;" :: "r"(s), "l"(gmem));
}
#define CP_COMMIT() asm volatile("cp.async.commit_group;")
#define CP_WAIT2()  asm volatile("cp.async.wait_group 2;")

// ---------------- 4-stage pipelined fp16 GEMM core ---------------------------
// 256 threads = 8 warps (2x4); warp tile 64x32; block tile 128x128; BK=32.
// A: [M][K] half K-major. B: [N][K] half K-major. f32 accumulate.
template <int KDIM>
__device__ __forceinline__ void gemm_f16(const __half* __restrict__ A,
                                         const __half* __restrict__ B,
                                         int lda, int ldb,
                                         int m0, int n0,
                                         float (&acc)[4][4][4]) {
    extern __shared__ __align__(16) __half sh[];
    __half* Abuf = sh;                        // STAGES * T_STAGE
    __half* Bbuf = sh + STAGES * T_STAGE;     // STAGES * T_STAGE

    const int tid  = threadIdx.x;
    const int lane = tid & 31;
    const int warp = tid >> 5;
    const int wr   = warp >> 2;   // 0..1 -> m offset 64
    const int wc   = warp & 3;    // 0..3 -> n offset 32
    const int gp   = lane >> 2;   // 0..7
    const int tg   = lane & 3;    // 0..3

    constexpr int NIT = KDIM / BK;

    // issue stage `it` into buffer it%STAGES; ALWAYS commits (group bookkeeping).
    auto issue = [&](int it) {
        if (it < NIT) {
            const int k0 = it * BK;
            __half* As = Abuf + (it % STAGES) * T_STAGE;
            __half* Bs = Bbuf + (it % STAGES) * T_STAGE;
            #pragma unroll
            for (int t = 0; t < 2; t++) {
                const int id = tid + t * 256;       // 0..511
                const int r  = id >> 2;             // 0..127
                const int c8 = (id & 3) * 8;        // halves: 0,8,16,24
                cp_async16(As + r * T_LD + c8,
                           A + (size_t)(m0 + r) * lda + k0 + c8);
            }
            #pragma unroll
            for (int t = 0; t < 2; t++) {
                const int id = tid + t * 256;
                const int r  = id >> 2;
                const int c8 = (id & 3) * 8;
                cp_async16(Bs + r * T_LD + c8,
                           B + (size_t)(n0 + r) * ldb + k0 + c8);
            }
        }
        CP_COMMIT();
    };

    issue(0);
    issue(1);
    issue(2);

    for (int it = 0; it < NIT; ++it) {
        CP_WAIT2();          // stage `it` resident; 2 newer stages in flight
        __syncthreads();     // also guards reuse of buffer (it+3)%4
        issue(it + 3);

        const __half* As = Abuf + (it % STAGES) * T_STAGE;
        const __half* Bs = Bbuf + (it % STAGES) * T_STAGE;

        #pragma unroll
        for (int kk = 0; kk < BK; kk += 16) {
            uint32_t a[4][4], b[4][2];
            #pragma unroll
            for (int mi = 0; mi < 4; mi++) {
                const int row = wr * 64 + mi * 16 + gp;
                a[mi][0] = *(const uint32_t*)&As[(row    ) * T_LD + kk + 2 * tg    ];
                a[mi][1] = *(const uint32_t*)&As[(row + 8) * T_LD + kk + 2 * tg    ];
                a[mi][2] = *(const uint32_t*)&As[(row    ) * T_LD + kk + 2 * tg + 8];
                a[mi][3] = *(const uint32_t*)&As[(row + 8) * T_LD + kk + 2 * tg + 8];
            }
            #pragma unroll
            for (int nj = 0; nj < 4; nj++) {
                const int col = wc * 32 + nj * 8 + gp;
                b[nj][0] = *(const uint32_t*)&Bs[col * T_LD + kk + 2 * tg    ];
                b[nj][1] = *(const uint32_t*)&Bs[col * T_LD + kk + 2 * tg + 8];
            }
            #pragma unroll
            for (int mi = 0; mi < 4; mi++)
                #pragma unroll
                for (int nj = 0; nj < 4; nj++)
                    mma_f16(acc[mi][nj], a[mi], b[nj]);
        }
    }
}

// Epilogue indices: m = m0 + wr*64 + mi*16 + gp + (e>=2 ? 8 : 0)
//                   n = n0 + wc*32 + nj*8 + 2*tg + (e&1)

// ---------------- prepasses --------------------------------------------------
__global__ __launch_bounds__(256) void k_round_h(const float4* __restrict__ src,
                                                 __half* __restrict__ dst, int n4) {
    const int i = blockIdx.x * 256 + threadIdx.x;
    if (i < n4) {
        const float4 v = src[i];
        __half2* d = (__half2*)(dst + i * 4);
        d[0] = __floats2half2_rn(v.x, v.y);
        d[1] = __floats2half2_rn(v.z, v.w);
    }
}

// transpose + fp16 round: src float [R][C] -> dst half [C][R], per-z slab
__global__ __launch_bounds__(256) void k_roundT_h(const float* __restrict__ src0,
                                                  __half* __restrict__ dst0,
                                                  int R, int C) {
    __shared__ __half t[32][33];
    const float*  src = src0 + (size_t)blockIdx.z * R * C;
    __half*       dst = dst0 + (size_t)blockIdx.z * R * C;
    const int r0 = blockIdx.y * 32, c0 = blockIdx.x * 32;
    const int tx = threadIdx.x & 31, ty = threadIdx.x >> 5;
    #pragma unroll
    for (int i = 0; i < 32; i += 8)
        t[ty + i][tx] = __float2half_rn(src[(size_t)(r0 + ty + i) * C + c0 + tx]);
    __syncthreads();
    #pragma unroll
    for (int i = 0; i < 32; i += 8)
        dst[(size_t)(c0 + ty + i) * R + r0 + tx] = t[tx][ty + i];
}

// ---------------- kernel 1: h = silu(X @ Wi + bi) -> u/v/q/k -----------------
__global__ __launch_bounds__(256, 2) void k_gemm1(const float* __restrict__ bi,
                                                  const float* __restrict__ gamma,
                                                  const float* __restrict__ beta) {
    float acc[4][4][4] = {};
    const int m0 = blockIdx.y * BM;
    const int n0 = blockIdx.x * BN;
    gemm_f16<HIDDEN>(g_hs, g_wiT, HIDDEN, HIDDEN, m0, n0, acc);

    const int lane = threadIdx.x & 31, warp = threadIdx.x >> 5;
    const int wr = warp >> 2, wc = warp & 3, gp = lane >> 2, tg = lane & 3;

    #pragma unroll
    for (int mi = 0; mi < 4; mi++)
        #pragma unroll
        for (int nj = 0; nj < 4; nj++)
            #pragma unroll
            for (int e = 0; e < 4; e++) {
                const int m = m0 + wr * 64 + mi * 16 + gp + ((e >> 1) << 3);
                const int n = n0 + wc * 32 + nj * 8 + 2 * tg + (e & 1);
                const float x = acc[mi][nj][e] + bi[n];
                const float sv = silu(x);
                if (n0 < INTER) {
                    g_u[(size_t)m * INTER + n] = sv;
                } else if (n0 < 2 * INTER) {
                    g_v[(size_t)m * INTER + (n - INTER)] = sv;
                } else {
                    const int c = n - 2 * INTER;
                    g_q[(size_t)m * KEY + c] =
                        __float2half_rn(sv * gamma[c] + beta[c]);
                    g_k[(size_t)m * KEY + c] =
                        __float2half_rn(sv * gamma[KEY + c] + beta[KEY + c]);
                }
            }
}

// ---------------- kernel 2: scores = q @ k^T / sqrt(KEY) + mask --------------
__global__ __launch_bounds__(256, 2) void k_scores(const int* __restrict__ mask) {
    const int b = blockIdx.z;
    float acc[4][4][4] = {};
    const int m0 = blockIdx.y * BM;
    const int n0 = blockIdx.x * BN;
    gemm_f16<KEY>(g_q + (size_t)b * SEQ * KEY,
                  g_k + (size_t)b * SEQ * KEY,
                  KEY, KEY, m0, n0, acc);

    float* sc = g_scores + (size_t)b * SEQ * SEQ;
    const float inv = 0.08838834764831845f;  // 1/sqrt(128)
    const int lane = threadIdx.x & 31, warp = threadIdx.x >> 5;
    const int wr = warp >> 2, wc = warp & 3, gp = lane >> 2, tg = lane & 3;

    #pragma unroll
    for (int nj = 0; nj < 4; nj++) {
        const int n = n0 + wc * 32 + nj * 8 + 2 * tg;
        const float am0 = (1.0f - (float)mask[b * SEQ + n    ]) * -1.0e12f;
        const float am1 = (1.0f - (float)mask[b * SEQ + n + 1]) * -1.0e12f;
        #pragma unroll
        for (int mi = 0; mi < 4; mi++) {
            const int m = m0 + wr * 64 + mi * 16 + gp;
            sc[(size_t)m * SEQ + n    ]       = acc[mi][nj][0] * inv + am0;
            sc[(size_t)m * SEQ + n + 1]       = acc[mi][nj][1] * inv + am1;
            sc[(size_t)(m + 8) * SEQ + n    ] = acc[mi][nj][2] * inv + am0;
            sc[(size_t)(m + 8) * SEQ + n + 1] = acc[mi][nj][3] * inv + am1;
        }
    }
}

// ---------------- kernel 3: length-scaled softmax -> half attn ---------------
__global__ __launch_bounds__(256) void k_softmax() {
    const float* sc = g_scores + (size_t)blockIdx.x * SEQ;
    __half*      at = g_attn   + (size_t)blockIdx.x * SEQ;
    const int tid = threadIdx.x;
    __shared__ float red[256];

    float vals[8];
    int cnt = 0;
    #pragma unroll
    for (int t = 0; t < 8; t++) {
        vals[t] = sc[tid + t * 256];
        cnt += (vals[t] > -1.0e11f) ? 1 : 0;
    }
    red[tid] = (float)cnt;
    __syncthreads();
    for (int s = 128; s > 0; s >>= 1) {
        if (tid < s) red[tid] += red[tid + s];
        __syncthreads();
    }
    const float l = fmaxf(red[0], 1.0f);
    const float scale = logf(l) * (1.0f / logf(512.0f));
    __syncthreads();

    float mx = -INFINITY;
    #pragma unroll
    for (int t = 0; t < 8; t++) {
        vals[t] *= scale;
        mx = fmaxf(mx, vals[t]);
    }
    red[tid] = mx;
    __syncthreads();
    for (int s = 128; s > 0; s >>= 1) {
        if (tid < s) red[tid] = fmaxf(red[tid], red[tid + s]);
        __syncthreads();
    }
    mx = red[0];
    __syncthreads();

    float sum = 0.0f;
    #pragma unroll
    for (int t = 0; t < 8; t++) {
        vals[t] = expf(vals[t] - mx);
        sum += vals[t];
    }
    red[tid] = sum;
    __syncthreads();
    for (int s = 128; s > 0; s >>= 1) {
        if (tid < s) red[tid] += red[tid + s];
        __syncthreads();
    }
    const float invsum = 1.0f / red[0];
    #pragma unroll
    for (int t = 0; t < 8; t++)
        at[tid + t * 256] = __float2half_rn(vals[t] * invsum);
}

// ---------------- kernel 4: g = half(u * (attn @ v)) -------------------------
__global__ __launch_bounds__(256, 2) void k_ctx() {
    const int b = blockIdx.z;
    float acc[4][4][4] = {};
    const int m0 = blockIdx.y * BM;
    const int n0 = blockIdx.x * BN;
    gemm_f16<SEQ>(g_attn + (size_t)b * SEQ * SEQ,
                  g_vT + (size_t)b * SEQ * INTER,
                  SEQ, SEQ, m0, n0, acc);

    const int lane = threadIdx.x & 31, warp = threadIdx.x >> 5;
    const int wr = warp >> 2, wc = warp & 3, gp = lane >> 2, tg = lane & 3;

    #pragma unroll
    for (int mi = 0; mi < 4; mi++)
        #pragma unroll
        for (int nj = 0; nj < 4; nj++)
            #pragma unroll
            for (int e = 0; e < 4; e++) {
                const int m = m0 + wr * 64 + mi * 16 + gp + ((e >> 1) << 3);
                const int n = n0 + wc * 32 + nj * 8 + 2 * tg + (e & 1);
                const size_t idx = ((size_t)b * SEQ + m) * INTER + n;
                g_g[idx] = __float2half_rn(g_u[idx] * acc[mi][nj][e]);
            }
}

// ---------------- kernel 5: out = g @ Wo + bo --------------------------------
__global__ __launch_bounds__(256, 2) void k_out(const float* __restrict__ bo,
                                                float* __restrict__ out) {
    float acc[4][4][4] = {};
    const int m0 = blockIdx.y * BM;
    const int n0 = blockIdx.x * BN;
    gemm_f16<INTER>(g_g, g_woT, INTER, INTER, m0, n0, acc);

    const int lane = threadIdx.x & 31, warp = threadIdx.x >> 5;
    const int wr = warp >> 2, wc = warp & 3, gp = lane >> 2, tg = lane & 3;

    #pragma unroll
    for (int mi = 0; mi < 4; mi++)
        #pragma unroll
        for (int nj = 0; nj < 4; nj++)
            #pragma unroll
            for (int e = 0; e < 4; e++) {
                const int m = m0 + wr * 64 + mi * 16 + gp + ((e >> 1) << 3);
                const int n = n0 + wc * 32 + nj * 8 + 2 * tg + (e & 1);
                out[(size_t)m * HIDDEN + n] = acc[mi][nj][e] + bo[n];
            }
}

// ---------------- launch ------------------------------------------------------
extern "C" void kernel_launch(void* const* d_in, const int* in_sizes, int n_in,
                              void* d_out, int out_size) {
    const float* hs    = (const float*)d_in[0];
    const int*   mask  = (const int*)  d_in[1];
    // d_in[2] = position_ids (unused)
    const float* Wi    = (const float*)d_in[3];
    const float* bi    = (const float*)d_in[4];
    const float* gamma = (const float*)d_in[5];
    const float* beta  = (const float*)d_in[6];
    const float* Wo    = (const float*)d_in[7];
    const float* bo    = (const float*)d_in[8];
    float* out = (float*)d_out;

    __half *p_hs, *p_wiT, *p_woT, *p_vT;
    float  *p_v;
    cudaGetSymbolAddress((void**)&p_hs,  g_hs);
    cudaGetSymbolAddress((void**)&p_wiT, g_wiT);
    cudaGetSymbolAddress((void**)&p_woT, g_woT);
    cudaGetSymbolAddress((void**)&p_v,   g_v);
    cudaGetSymbolAddress((void**)&p_vT,  g_vT);

    cudaFuncSetAttribute(k_gemm1,  cudaFuncAttributeMaxDynamicSharedMemorySize, SMEM_BYTES);
    cudaFuncSetAttribute(k_scores, cudaFuncAttributeMaxDynamicSharedMemorySize, SMEM_BYTES);
    cudaFuncSetAttribute(k_ctx,    cudaFuncAttributeMaxDynamicSharedMemorySize, SMEM_BYTES);
    cudaFuncSetAttribute(k_out,    cudaFuncAttributeMaxDynamicSharedMemorySize, SMEM_BYTES);

    dim3 blk(256);
    {   // hs -> half
        const int n4 = M_TOT * HIDDEN / 4;
        k_round_h<<<(n4 + 255) / 256, blk>>>((const float4*)hs, p_hs, n4);
    }
    // Wi [768][3200] -> WiT half [3200][768]
    k_roundT_h<<<dim3(N1 / 32, HIDDEN / 32, 1), blk>>>(Wi, p_wiT, HIDDEN, N1);
    // Wo [1536][768] -> WoT half [768][1536]
    k_roundT_h<<<dim3(HIDDEN / 32, INTER / 32, 1), blk>>>(Wo, p_woT, INTER, HIDDEN);

    k_gemm1<<<dim3(N1 / BN, M_TOT / BM), blk, SMEM_BYTES>>>(bi, gamma, beta);

    // v fp32 [SEQ][INTER] -> vT half [INTER][SEQ] per batch
    k_roundT_h<<<dim3(INTER / 32, SEQ / 32, BDIM), blk>>>(p_v, p_vT, SEQ, INTER);

    k_scores<<<dim3(SEQ / BN, SEQ / BM, BDIM), blk, SMEM_BYTES>>>(mask);
    k_softmax<<<dim3(M_TOT), blk>>>();
    k_ctx<<<dim3(INTER / BN, SEQ / BM, BDIM), blk, SMEM_BYTES>>>();
    k_out<<<dim3(HIDDEN / BN, M_TOT / BM), blk, SMEM_BYTES>>>(bo, out);
}

// round 8
// speedup vs baseline: 1.6952x; 1.1003x over previous
#include <cuda_runtime.h>
#include <cuda_fp16.h>
#include <math.h>
#include <stdint.h>

#define HIDDEN 768
#define KEY    128
#define INTER  1536
#define BDIM   4
#define SEQ    2048
#define M_TOT  (BDIM*SEQ)        // 8192
#define N1     (2*INTER+KEY)     // 3200

#define BM 128
#define BN 128
#define BK 32                    // 32 halves = 64 B per row
#define STAGES 4
#define T_LD 40                  // halves per row; ldmatrix rows land on disjoint bank quads
#define T_STAGE (128 * T_LD)     // halves per tile per stage
#define SMEM_BYTES (STAGES * 2 * T_STAGE * 2)   // 81,920 B

// ---------------- scratch (device globals; no allocation allowed) ----------
__device__ float  g_u[(size_t)M_TOT * INTER];          // u raw fp32
__device__ float  g_v[(size_t)M_TOT * INTER];          // v raw fp32 (transpose source)
__device__ __half g_vT[(size_t)M_TOT * INTER];         // v^T per batch [INTER][SEQ]
__device__ __half g_q[(size_t)M_TOT * KEY];            // q half [m][KEY]
__device__ __half g_k[(size_t)M_TOT * KEY];            // k half [m][KEY]
__device__ float  g_scores[(size_t)BDIM * SEQ * SEQ];  // scores fp32
__device__ __half g_attn[(size_t)BDIM * SEQ * SEQ];    // softmax(attn) half
__device__ __half g_g[(size_t)M_TOT * INTER];          // half(u*ctx)
__device__ __half g_hs[(size_t)M_TOT * HIDDEN];        // half hidden_states
__device__ __half g_wiT[(size_t)N1 * HIDDEN];          // Wi^T [N1][HIDDEN]
__device__ __half g_woT[(size_t)HIDDEN * INTER];       // Wo^T [HIDDEN][INTER]

// ---------------- helpers ---------------------------------------------------
__device__ __forceinline__ float silu(float x) { return x / (1.0f + expf(-x)); }

__device__ __forceinline__ void mma_f16(float (&c)[4], const uint32_t (&a)[4],
                                        const uint32_t (&b)[2]) {
    asm volatile(
        "mma.sync.aligned.m16n8k16.row.col.f32.f16.f16.f32 "
        "{%0,%1,%2,%3}, {%4,%5,%6,%7}, {%8,%9}, {%0,%1,%2,%3};"
        : "+f"(c[0]), "+f"(c[1]), "+f"(c[2]), "+f"(c[3])
        : "r"(a[0]), "r"(a[1]), "r"(a[2]), "r"(a[3]), "r"(b[0]), "r"(b[1]));
}

__device__ __forceinline__ void ldsm4(uint32_t& r0, uint32_t& r1,
                                      uint32_t& r2, uint32_t& r3, uint32_t addr) {
    asm volatile("ldmatrix.sync.aligned.m8n8.x4.shared.b16 {%0,%1,%2,%3}, [%4];"
                 : "=r"(r0), "=r"(r1), "=r"(r2), "=r"(r3) : "r"(addr));
}

__device__ __forceinline__ void cp_async16(const __half* smem, const __half* gmem) {
    uint32_t s = (uint32_t)__cvta_generic_to_shared(smem);
    asm volatile("cp.async.cg.shared.global [%0], [%1], 16;" :: "r"(s), "l"(gmem));
}
#define CP_COMMIT() asm volatile("cp.async.commit_group;")
#define CP_WAIT2()  asm volatile("cp.async.wait_group 2;")

// ---------------- 4-stage pipelined fp16 GEMM core (ldmatrix) ----------------
// 256 threads = 8 warps (2x4); warp tile 64x32; block tile 128x128; BK=32.
// A: [M][K] half K-major. B: [N][K] half K-major. f32 accumulate.
template <int KDIM>
__device__ __forceinline__ void gemm_f16(const __half* __restrict__ A,
                                         const __half* __restrict__ B,
                                         int lda, int ldb,
                                         int m0, int n0,
                                         float (&acc)[4][4][4]) {
    extern __shared__ __align__(16) __half sh[];
    __half* Abuf = sh;                        // STAGES * T_STAGE
    __half* Bbuf = sh + STAGES * T_STAGE;     // STAGES * T_STAGE

    const int tid  = threadIdx.x;
    const int lane = tid & 31;
    const int warp = tid >> 5;
    const int wr   = warp >> 2;   // 0..1 -> m offset 64
    const int wc   = warp & 3;    // 0..3 -> n offset 32

    // per-lane ldmatrix byte offsets (within a stage buffer)
    const int lr = lane & 7;
    const int a_row = lr + ((lane >> 3) & 1) * 8;   // tiles: (k0,m0)(k0,m8)(k8,m0)(k8,m8)
    const int a_k   = (lane >> 4) * 8;
    uint32_t offA[4], offB[2];
    #pragma unroll
    for (int mi = 0; mi < 4; mi++)
        offA[mi] = ((wr * 64 + mi * 16 + a_row) * T_LD + a_k) * 2;
    {
        const int t = lane >> 3;                    // tiles: (n0,k0)(n0,k8)(n8,k0)(n8,k8)
        const int b_n = (t >> 1) * 8;
        const int b_k = (t & 1) * 8;
        #pragma unroll
        for (int p = 0; p < 2; p++)
            offB[p] = ((wc * 32 + p * 16 + b_n + lr) * T_LD + b_k) * 2;
    }
    const uint32_t smbA = (uint32_t)__cvta_generic_to_shared(Abuf);
    const uint32_t smbB = (uint32_t)__cvta_generic_to_shared(Bbuf);

    constexpr int NIT = KDIM / BK;

    auto issue = [&](int it) {
        if (it < NIT) {
            const int k0 = it * BK;
            __half* As = Abuf + (it % STAGES) * T_STAGE;
            __half* Bs = Bbuf + (it % STAGES) * T_STAGE;
            #pragma unroll
            for (int t = 0; t < 2; t++) {
                const int id = tid + t * 256;       // 0..511
                const int r  = id >> 2;             // 0..127
                const int c8 = (id & 3) * 8;        // halves: 0,8,16,24
                cp_async16(As + r * T_LD + c8,
                           A + (size_t)(m0 + r) * lda + k0 + c8);
            }
            #pragma unroll
            for (int t = 0; t < 2; t++) {
                const int id = tid + t * 256;
                const int r  = id >> 2;
                const int c8 = (id & 3) * 8;
                cp_async16(Bs + r * T_LD + c8,
                           B + (size_t)(n0 + r) * ldb + k0 + c8);
            }
        }
        CP_COMMIT();
    };

    issue(0);
    issue(1);
    issue(2);

    for (int it = 0; it < NIT; ++it) {
        CP_WAIT2();          // stage `it` resident; 2 newer stages in flight
        __syncthreads();     // also guards reuse of buffer (it+3)%4
        issue(it + 3);

        const uint32_t As = smbA + (uint32_t)((it % STAGES) * T_STAGE * 2);
        const uint32_t Bs = smbB + (uint32_t)((it % STAGES) * T_STAGE * 2);

        #pragma unroll
        for (int kk = 0; kk < BK; kk += 16) {
            uint32_t a[4][4], b[4][2];
            #pragma unroll
            for (int mi = 0; mi < 4; mi++)
                ldsm4(a[mi][0], a[mi][1], a[mi][2], a[mi][3],
                      As + offA[mi] + kk * 2);
            ldsm4(b[0][0], b[0][1], b[1][0], b[1][1], Bs + offB[0] + kk * 2);
            ldsm4(b[2][0], b[2][1], b[3][0], b[3][1], Bs + offB[1] + kk * 2);
            #pragma unroll
            for (int mi = 0; mi < 4; mi++)
                #pragma unroll
                for (int nj = 0; nj < 4; nj++)
                    mma_f16(acc[mi][nj], a[mi], b[nj]);
        }
    }
}

// Epilogue indices: m = m0 + wr*64 + mi*16 + gp + (e>=2 ? 8 : 0)
//                   n = n0 + wc*32 + nj*8 + 2*tg + (e&1)

// ---------------- prepasses --------------------------------------------------
__global__ __launch_bounds__(256) void k_round_h(const float4* __restrict__ src,
                                                 __half* __restrict__ dst, int n4) {
    const int i = blockIdx.x * 256 + threadIdx.x;
    if (i < n4) {
        const float4 v = src[i];
        __half2* d = (__half2*)(dst + i * 4);
        d[0] = __floats2half2_rn(v.x, v.y);
        d[1] = __floats2half2_rn(v.z, v.w);
    }
}

// transpose + fp16 round: src float [R][C] -> dst half [C][R], per-z slab
__global__ __launch_bounds__(256) void k_roundT_h(const float* __restrict__ src0,
                                                  __half* __restrict__ dst0,
                                                  int R, int C) {
    __shared__ __half t[32][33];
    const float*  src = src0 + (size_t)blockIdx.z * R * C;
    __half*       dst = dst0 + (size_t)blockIdx.z * R * C;
    const int r0 = blockIdx.y * 32, c0 = blockIdx.x * 32;
    const int tx = threadIdx.x & 31, ty = threadIdx.x >> 5;
    #pragma unroll
    for (int i = 0; i < 32; i += 8)
        t[ty + i][tx] = __float2half_rn(src[(size_t)(r0 + ty + i) * C + c0 + tx]);
    __syncthreads();
    #pragma unroll
    for (int i = 0; i < 32; i += 8)
        dst[(size_t)(c0 + ty + i) * R + r0 + tx] = t[tx][ty + i];
}

// ---------------- kernel 1: h = silu(X @ Wi + bi) -> u/v/q/k -----------------
__global__ __launch_bounds__(256, 2) void k_gemm1(const float* __restrict__ bi,
                                                  const float* __restrict__ gamma,
                                                  const float* __restrict__ beta) {
    float acc[4][4][4] = {};
    const int m0 = blockIdx.y * BM;
    const int n0 = blockIdx.x * BN;
    gemm_f16<HIDDEN>(g_hs, g_wiT, HIDDEN, HIDDEN, m0, n0, acc);

    const int lane = threadIdx.x & 31, warp = threadIdx.x >> 5;
    const int wr = warp >> 2, wc = warp & 3, gp = lane >> 2, tg = lane & 3;

    #pragma unroll
    for (int mi = 0; mi < 4; mi++)
        #pragma unroll
        for (int nj = 0; nj < 4; nj++)
            #pragma unroll
            for (int e = 0; e < 4; e++) {
                const int m = m0 + wr * 64 + mi * 16 + gp + ((e >> 1) << 3);
                const int n = n0 + wc * 32 + nj * 8 + 2 * tg + (e & 1);
                const float x = acc[mi][nj][e] + bi[n];
                const float sv = silu(x);
                if (n0 < INTER) {
                    g_u[(size_t)m * INTER + n] = sv;
                } else if (n0 < 2 * INTER) {
                    g_v[(size_t)m * INTER + (n - INTER)] = sv;
                } else {
                    const int c = n - 2 * INTER;
                    g_q[(size_t)m * KEY + c] =
                        __float2half_rn(sv * gamma[c] + beta[c]);
                    g_k[(size_t)m * KEY + c] =
                        __float2half_rn(sv * gamma[KEY + c] + beta[KEY + c]);
                }
            }
}

// ---------------- kernel 2: scores = q @ k^T / sqrt(KEY) + mask --------------
__global__ __launch_bounds__(256, 2) void k_scores(const int* __restrict__ mask) {
    const int b = blockIdx.z;
    float acc[4][4][4] = {};
    const int m0 = blockIdx.y * BM;
    const int n0 = blockIdx.x * BN;
    gemm_f16<KEY>(g_q + (size_t)b * SEQ * KEY,
                  g_k + (size_t)b * SEQ * KEY,
                  KEY, KEY, m0, n0, acc);

    float* sc = g_scores + (size_t)b * SEQ * SEQ;
    const float inv = 0.08838834764831845f;  // 1/sqrt(128)
    const int lane = threadIdx.x & 31, warp = threadIdx.x >> 5;
    const int wr = warp >> 2, wc = warp & 3, gp = lane >> 2, tg = lane & 3;

    #pragma unroll
    for (int nj = 0; nj < 4; nj++) {
        const int n = n0 + wc * 32 + nj * 8 + 2 * tg;
        const float am0 = (1.0f - (float)mask[b * SEQ + n    ]) * -1.0e12f;
        const float am1 = (1.0f - (float)mask[b * SEQ + n + 1]) * -1.0e12f;
        #pragma unroll
        for (int mi = 0; mi < 4; mi++) {
            const int m = m0 + wr * 64 + mi * 16 + gp;
            sc[(size_t)m * SEQ + n    ]       = acc[mi][nj][0] * inv + am0;
            sc[(size_t)m * SEQ + n + 1]       = acc[mi][nj][1] * inv + am1;
            sc[(size_t)(m + 8) * SEQ + n    ] = acc[mi][nj][2] * inv + am0;
            sc[(size_t)(m + 8) * SEQ + n + 1] = acc[mi][nj][3] * inv + am1;
        }
    }
}

// ---------------- kernel 3: length-scaled softmax -> half attn ---------------
__global__ __launch_bounds__(256) void k_softmax() {
    const float* sc = g_scores + (size_t)blockIdx.x * SEQ;
    __half*      at = g_attn   + (size_t)blockIdx.x * SEQ;
    const int tid = threadIdx.x;
    __shared__ float red[256];

    float vals[8];
    int cnt = 0;
    #pragma unroll
    for (int t = 0; t < 8; t++) {
        vals[t] = sc[tid + t * 256];
        cnt += (vals[t] > -1.0e11f) ? 1 : 0;
    }
    red[tid] = (float)cnt;
    __syncthreads();
    for (int s = 128; s > 0; s >>= 1) {
        if (tid < s) red[tid] += red[tid + s];
        __syncthreads();
    }
    const float l = fmaxf(red[0], 1.0f);
    const float scale = logf(l) * (1.0f / logf(512.0f));
    __syncthreads();

    float mx = -INFINITY;
    #pragma unroll
    for (int t = 0; t < 8; t++) {
        vals[t] *= scale;
        mx = fmaxf(mx, vals[t]);
    }
    red[tid] = mx;
    __syncthreads();
    for (int s = 128; s > 0; s >>= 1) {
        if (tid < s) red[tid] = fmaxf(red[tid], red[tid + s]);
        __syncthreads();
    }
    mx = red[0];
    __syncthreads();

    float sum = 0.0f;
    #pragma unroll
    for (int t = 0; t < 8; t++) {
        vals[t] = expf(vals[t] - mx);
        sum += vals[t];
    }
    red[tid] = sum;
    __syncthreads();
    for (int s = 128; s > 0; s >>= 1) {
        if (tid < s) red[tid] += red[tid + s];
        __syncthreads();
    }
    const float invsum = 1.0f / red[0];
    #pragma unroll
    for (int t = 0; t < 8; t++)
        at[tid + t * 256] = __float2half_rn(vals[t] * invsum);
}

// ---------------- kernel 4: g = half(u * (attn @ v)) -------------------------
__global__ __launch_bounds__(256, 2) void k_ctx() {
    const int b = blockIdx.z;
    float acc[4][4][4] = {};
    const int m0 = blockIdx.y * BM;
    const int n0 = blockIdx.x * BN;
    gemm_f16<SEQ>(g_attn + (size_t)b * SEQ * SEQ,
                  g_vT + (size_t)b * SEQ * INTER,
                  SEQ, SEQ, m0, n0, acc);

    const int lane = threadIdx.x & 31, warp = threadIdx.x >> 5;
    const int wr = warp >> 2, wc = warp & 3, gp = lane >> 2, tg = lane & 3;

    #pragma unroll
    for (int mi = 0; mi < 4; mi++)
        #pragma unroll
        for (int nj = 0; nj < 4; nj++)
            #pragma unroll
            for (int e = 0; e < 4; e++) {
                const int m = m0 + wr * 64 + mi * 16 + gp + ((e >> 1) << 3);
                const int n = n0 + wc * 32 + nj * 8 + 2 * tg + (e & 1);
                const size_t idx = ((size_t)b * SEQ + m) * INTER + n;
                g_g[idx] = __float2half_rn(g_u[idx] * acc[mi][nj][e]);
            }
}

// ---------------- kernel 5: out = g @ Wo + bo --------------------------------
__global__ __launch_bounds__(256, 2) void k_out(const float* __restrict__ bo,
                                                float* __restrict__ out) {
    float acc[4][4][4] = {};
    const int m0 = blockIdx.y * BM;
    const int n0 = blockIdx.x * BN;
    gemm_f16<INTER>(g_g, g_woT, INTER, INTER, m0, n0, acc);

    const int lane = threadIdx.x & 31, warp = threadIdx.x >> 5;
    const int wr = warp >> 2, wc = warp & 3, gp = lane >> 2, tg = lane & 3;

    #pragma unroll
    for (int mi = 0; mi < 4; mi++)
        #pragma unroll
        for (int nj = 0; nj < 4; nj++)
            #pragma unroll
            for (int e = 0; e < 4; e++) {
                const int m = m0 + wr * 64 + mi * 16 + gp + ((e >> 1) << 3);
                const int n = n0 + wc * 32 + nj * 8 + 2 * tg + (e & 1);
                out[(size_t)m * HIDDEN + n] = acc[mi][nj][e] + bo[n];
            }
}

// ---------------- launch ------------------------------------------------------
extern "C" void kernel_launch(void* const* d_in, const int* in_sizes, int n_in,
                              void* d_out, int out_size) {
    const float* hs    = (const float*)d_in[0];
    const int*   mask  = (const int*)  d_in[1];
    // d_in[2] = position_ids (unused)
    const float* Wi    = (const float*)d_in[3];
    const float* bi    = (const float*)d_in[4];
    const float* gamma = (const float*)d_in[5];
    const float* beta  = (const float*)d_in[6];
    const float* Wo    = (const float*)d_in[7];
    const float* bo    = (const float*)d_in[8];
    float* out = (float*)d_out;

    __half *p_hs, *p_wiT, *p_woT, *p_vT;
    float  *p_v;
    cudaGetSymbolAddress((void**)&p_hs,  g_hs);
    cudaGetSymbolAddress((void**)&p_wiT, g_wiT);
    cudaGetSymbolAddress((void**)&p_woT, g_woT);
    cudaGetSymbolAddress((void**)&p_v,   g_v);
    cudaGetSymbolAddress((void**)&p_vT,  g_vT);

    cudaFuncSetAttribute(k_gemm1,  cudaFuncAttributeMaxDynamicSharedMemorySize, SMEM_BYTES);
    cudaFuncSetAttribute(k_scores, cudaFuncAttributeMaxDynamicSharedMemorySize, SMEM_BYTES);
    cudaFuncSetAttribute(k_ctx,    cudaFuncAttributeMaxDynamicSharedMemorySize, SMEM_BYTES);
    cudaFuncSetAttribute(k_out,    cudaFuncAttributeMaxDynamicSharedMemorySize, SMEM_BYTES);

    dim3 blk(256);
    {   // hs -> half
        const int n4 = M_TOT * HIDDEN / 4;
        k_round_h<<<(n4 + 255) / 256, blk>>>((const float4*)hs, p_hs, n4);
    }
    // Wi [768][3200] -> WiT half [3200][768]
    k_roundT_h<<<dim3(N1 / 32, HIDDEN / 32, 1), blk>>>(Wi, p_wiT, HIDDEN, N1);
    // Wo [1536][768] -> WoT half [768][1536]
    k_roundT_h<<<dim3(HIDDEN / 32, INTER / 32, 1), blk>>>(Wo, p_woT, INTER, HIDDEN);

    k_gemm1<<<dim3(N1 / BN, M_TOT / BM), blk, SMEM_BYTES>>>(bi, gamma, beta);

    // v fp32 [SEQ][INTER] -> vT half [INTER][SEQ] per batch
    k_roundT_h<<<dim3(INTER / 32, SEQ / 32, BDIM), blk>>>(p_v, p_vT, SEQ, INTER);

    k_scores<<<dim3(SEQ / BN, SEQ / BM, BDIM), blk, SMEM_BYTES>>>(mask);
    k_softmax<<<dim3(M_TOT), blk>>>();
    k_ctx<<<dim3(INTER / BN, SEQ / BM, BDIM), blk, SMEM_BYTES>>>();
    k_out<<<dim3(HIDDEN / BN, M_TOT / BM), blk, SMEM_BYTES>>>(bo, out);
}